// round 15
// baseline (speedup 1.0000x reference)
#include <cuda_runtime.h>
#include <math.h>

#define B2 2
#define C 256
#define HH 128
#define WW 128
#define NB (B2*WW)       // 256
#define O2 512           // 2*DEPTH
#define NH 8
#define KK 128
#define REL (2*KK-1)     // 255
#define EPSBN 1e-5f

// ---------------- device scratch ----------------
__device__ float g_xf[(size_t)NB*C*HH];        // [b][c][h]
__device__ float g_kqv[(size_t)NB*O2*HH];      // [b][o][h]
__device__ float g_qk[(size_t)NB*NH*KK*KK];
__device__ float g_qr[(size_t)NB*NH*KK*KK];
__device__ float g_kr[(size_t)NB*NH*KK*KK];
__device__ float g_attn[(size_t)NB*256*KK];    // [b][head*32+d][x]
__device__ float g_ks[O2], g_kt[O2];           // kqv BN scale/shift
__device__ float g_part[NB*NH*6];              // per-(b,head) logits BN partials
__device__ float g_ls[24], g_lt[24];           // logits BN scale/shift

// ---------------- kernel 1: x (B,C,H,W) -> xf [(b0*W+w)][c][h] ----------------
__global__ void transpose_x(const float* __restrict__ x) {
    __shared__ float tile[32][33];
    int plane = blockIdx.z;              // b0*C + c
    int b0 = plane >> 8, c = plane & 255;
    int h0 = blockIdx.y * 32, w0 = blockIdx.x * 32;
    const float* src = x + (size_t)plane * HH * WW;
    int tx = threadIdx.x;
    for (int i = threadIdx.y; i < 32; i += 8)
        tile[i][tx] = src[(size_t)(h0 + i) * WW + w0 + tx];
    __syncthreads();
    for (int i = threadIdx.y; i < 32; i += 8) {
        int w = w0 + i;
        g_xf[(size_t)(b0 * WW + w) * C * HH + (size_t)c * HH + h0 + tx] = tile[tx][i];
    }
}

// ---------------- kernel 2: kqv[b][o][h] = sum_c w[o][c] * xf[b][c][h] ----------------
__global__ void __launch_bounds__(256) gemm_kqv(const float* __restrict__ wkqv) {
    __shared__ float As[16][128];   // [k][o]
    __shared__ float Bs[16][128];   // [k][h]
    int b = blockIdx.y;
    int otile = blockIdx.x;          // 0..3
    int tid = threadIdx.x;
    int tx = tid & 15, ty = tid >> 4;
    const float* xfb = g_xf + (size_t)b * C * HH;
    float acc[8][8];
    #pragma unroll
    for (int i = 0; i < 8; i++)
        #pragma unroll
        for (int j = 0; j < 8; j++) acc[i][j] = 0.f;

    int ai = tid & 127;
    int aj = (tid >> 7) * 8;
    for (int kc = 0; kc < C; kc += 16) {
        const float* wrow = wkqv + (size_t)(otile * 128 + ai) * C + kc + aj;
        float4 a0 = *(const float4*)(wrow);
        float4 a1 = *(const float4*)(wrow + 4);
        As[aj + 0][ai] = a0.x; As[aj + 1][ai] = a0.y;
        As[aj + 2][ai] = a0.z; As[aj + 3][ai] = a0.w;
        As[aj + 4][ai] = a1.x; As[aj + 5][ai] = a1.y;
        As[aj + 6][ai] = a1.z; As[aj + 7][ai] = a1.w;
        #pragma unroll
        for (int t = 0; t < 2; t++) {
            int l = tid + t * 256;       // 0..511
            int j = l >> 5;              // 0..15
            int h4 = (l & 31) * 4;
            *(float4*)&Bs[j][h4] = *(const float4*)(xfb + (size_t)(kc + j) * HH + h4);
        }
        __syncthreads();
        #pragma unroll
        for (int k = 0; k < 16; k++) {
            float af[8], bf[8];
            *(float4*)(af)     = *(float4*)&As[k][ty * 8];
            *(float4*)(af + 4) = *(float4*)&As[k][ty * 8 + 4];
            *(float4*)(bf)     = *(float4*)&Bs[k][tx * 8];
            *(float4*)(bf + 4) = *(float4*)&Bs[k][tx * 8 + 4];
            #pragma unroll
            for (int i = 0; i < 8; i++)
                #pragma unroll
                for (int j = 0; j < 8; j++)
                    acc[i][j] = fmaf(af[i], bf[j], acc[i][j]);
        }
        __syncthreads();
    }
    float* outb = g_kqv + (size_t)b * O2 * HH + (size_t)(otile * 128) * HH;
    #pragma unroll
    for (int i = 0; i < 8; i++) {
        float* row = outb + (size_t)(ty * 8 + i) * HH + tx * 8;
        *(float4*)(row)     = *(float4*)&acc[i][0];
        *(float4*)(row + 4) = *(float4*)&acc[i][4];
    }
}

// ---------------- kernel 3: kqv BN stats per channel o ----------------
__global__ void bn_kqv_stats(const float* __restrict__ gamma, const float* __restrict__ beta) {
    int o = blockIdx.x;
    float s = 0.f, sq = 0.f;
    for (int idx = threadIdx.x; idx < NB * HH; idx += 256) {
        int b = idx >> 7, h = idx & 127;
        float v = g_kqv[(size_t)b * O2 * HH + (size_t)o * HH + h];
        s += v; sq += v * v;
    }
    __shared__ float rs[8], rq[8];
    int wid = threadIdx.x >> 5, lane = threadIdx.x & 31;
    #pragma unroll
    for (int off = 16; off; off >>= 1) {
        s  += __shfl_down_sync(0xffffffffu, s, off);
        sq += __shfl_down_sync(0xffffffffu, sq, off);
    }
    if (!lane) { rs[wid] = s; rq[wid] = sq; }
    __syncthreads();
    if (threadIdx.x == 0) {
        float ts = 0.f, tq = 0.f;
        #pragma unroll
        for (int w = 0; w < 8; w++) { ts += rs[w]; tq += rq[w]; }
        float n = (float)(NB * HH);
        float mean = ts / n;
        float var = tq / n - mean * mean;
        float sc = gamma[o] * rsqrtf(var + EPSBN);
        g_ks[o] = sc;
        g_kt[o] = beta[o] - mean * sc;
    }
}

// ---------------- kernel 4: logits qk/qr/kr per (b, head) + BN partials ----------------
__global__ void __launch_bounds__(256) logits_kernel(const float* __restrict__ rel) {
    __shared__ float sq[16][128], sk[16][128];
    __shared__ float sqe[16][REL], ske[16][REL];
    int bh = blockIdx.x;
    int b = bh >> 3, hh = bh & 7;
    int tid = threadIdx.x;
    const float* kqvb = g_kqv + (size_t)b * O2 * HH;

    for (int idx = tid; idx < 16 * 128; idx += 256) {
        int d = idx >> 7, h = idx & 127;
        int ok = hh * 64 + d;
        int oq = ok + 16;
        sk[d][h] = kqvb[(size_t)ok * HH + h] * g_ks[ok] + g_kt[ok];
        sq[d][h] = kqvb[(size_t)oq * HH + h] * g_ks[oq] + g_kt[oq];
    }
    for (int idx = tid; idx < 16 * REL; idx += 256) {
        int d = idx / REL, i = idx % REL;
        sqe[d][i] = rel[(size_t)d * REL + i];
        ske[d][i] = rel[(size_t)(16 + d) * REL + i];
    }
    __syncthreads();

    float aqk = 0, aqk2 = 0, aqr = 0, aqr2 = 0, akr = 0, akr2 = 0;
    int wid = tid >> 5, lane = tid & 31;
    size_t base = (size_t)bh * KK * KK;
    for (int r = 0; r < 16; r++) {
        int x = wid * 16 + r;
        float qreg[16];
        #pragma unroll
        for (int d = 0; d < 16; d++) qreg[d] = sq[d][x];
        #pragma unroll
        for (int j = 0; j < 4; j++) {
            int y = lane + 32 * j;
            int iq = y - x + 127;
            int ik = x - y + 127;
            float vqk = 0.f, vqr = 0.f, vkr = 0.f;
            #pragma unroll
            for (int d = 0; d < 16; d++) {
                float kd = sk[d][y];
                vqk = fmaf(qreg[d], kd, vqk);
                vqr = fmaf(qreg[d], sqe[d][iq], vqr);
                vkr = fmaf(kd, ske[d][ik], vkr);
            }
            size_t oidx = base + (size_t)x * KK + y;
            g_qk[oidx] = vqk;
            g_qr[oidx] = vqr;
            g_kr[oidx] = vkr;
            aqk += vqk; aqk2 = fmaf(vqk, vqk, aqk2);
            aqr += vqr; aqr2 = fmaf(vqr, vqr, aqr2);
            akr += vkr; akr2 = fmaf(vkr, vkr, akr2);
        }
    }
    // block reduction of 6 partials (deterministic; no atomics)
    float vals[6] = {aqk, aqk2, aqr, aqr2, akr, akr2};
    #pragma unroll
    for (int v = 0; v < 6; v++)
        #pragma unroll
        for (int off = 16; off; off >>= 1)
            vals[v] += __shfl_down_sync(0xffffffffu, vals[v], off);
    __syncthreads();                 // everyone done reading sq
    float* red = &sq[0][0];          // reuse smem (8 warps * 6)
    if (!lane) {
        #pragma unroll
        for (int v = 0; v < 6; v++) red[wid * 6 + v] = vals[v];
    }
    __syncthreads();
    if (tid < 6) {
        float t = 0.f;
        #pragma unroll
        for (int w = 0; w < 8; w++) t += red[w * 6 + tid];
        g_part[(size_t)bh * 6 + tid] = t;   // order: qk_s,qk_q, qr_s,qr_q, kr_s,kr_q
    }
}

// ---------------- kernel 5: finalize logits BN (deterministic) ----------------
__global__ void finalize_logits(const float* __restrict__ lg, const float* __restrict__ lb) {
    int c = blockIdx.x;              // 0..23
    int comp = c >> 3, hh = c & 7;
    int t = threadIdx.x;             // 0..255 -> b
    float s  = g_part[(size_t)(t * 8 + hh) * 6 + comp * 2];
    float sq = g_part[(size_t)(t * 8 + hh) * 6 + comp * 2 + 1];
    __shared__ float rs[8], rq[8];
    int wid = t >> 5, lane = t & 31;
    #pragma unroll
    for (int off = 16; off; off >>= 1) {
        s  += __shfl_down_sync(0xffffffffu, s, off);
        sq += __shfl_down_sync(0xffffffffu, sq, off);
    }
    if (!lane) { rs[wid] = s; rq[wid] = sq; }
    __syncthreads();
    if (t == 0) {
        float ts = 0.f, tq = 0.f;
        #pragma unroll
        for (int w = 0; w < 8; w++) { ts += rs[w]; tq += rq[w]; }
        float n = (float)NB * KK * KK;   // 4194304
        float mean = ts / n;
        float var = tq / n - mean * mean;
        float sc = lg[c] * rsqrtf(var + EPSBN);
        g_ls[c] = sc;
        g_lt[c] = lb[c] - mean * sc;
    }
}

// ---------------- kernel 6: softmax + attn + attn_enc per (b, head) ----------------
#define SMEM_F_FLOATS (128*33 + 255*33 + 8*128 + 32*129)
__global__ void __launch_bounds__(256) attn_kernel(const float* __restrict__ rel) {
    extern __shared__ float smemF[];
    float* sv   = smemF;                  // [y][d] stride 33
    float* sve  = sv + 128 * 33;          // [idx][d] stride 33
    float* wbuf = sve + 255 * 33;         // [warp][y] stride 128
    float* obuf = wbuf + 8 * 128;         // [d][x] stride 129

    int bh = blockIdx.x;
    int b = bh >> 3, hh = bh & 7;
    int tid = threadIdx.x;
    const float* kqvb = g_kqv + (size_t)b * O2 * HH;

    for (int idx = tid; idx < 32 * 128; idx += 256) {
        int d = idx >> 7, y = idx & 127;
        int o = hh * 64 + 32 + d;
        sv[y * 33 + d] = kqvb[(size_t)o * HH + y] * g_ks[o] + g_kt[o];
    }
    for (int idx = tid; idx < 32 * REL; idx += 256) {
        int d = idx / REL, i = idx % REL;
        sve[i * 33 + d] = rel[(size_t)(32 + d) * REL + i];
    }
    float s0 = g_ls[hh], s1 = g_ls[8 + hh], s2 = g_ls[16 + hh];
    float tt = g_lt[hh] + g_lt[8 + hh] + g_lt[16 + hh];
    __syncthreads();

    int wid = tid >> 5, lane = tid & 31;
    size_t base = (size_t)bh * KK * KK;
    for (int r = 0; r < 16; r++) {
        int x = wid * 16 + r;
        float L[4];
        #pragma unroll
        for (int j = 0; j < 4; j++) {
            size_t idx = base + (size_t)x * KK + lane + 32 * j;
            L[j] = g_qk[idx] * s0 + g_qr[idx] * s1 + g_kr[idx] * s2 + tt;
        }
        float m = fmaxf(fmaxf(L[0], L[1]), fmaxf(L[2], L[3]));
        #pragma unroll
        for (int off = 16; off; off >>= 1)
            m = fmaxf(m, __shfl_xor_sync(0xffffffffu, m, off));
        float ssum = 0.f;
        #pragma unroll
        for (int j = 0; j < 4; j++) { L[j] = expf(L[j] - m); ssum += L[j]; }
        #pragma unroll
        for (int off = 16; off; off >>= 1)
            ssum += __shfl_xor_sync(0xffffffffu, ssum, off);
        float inv = 1.0f / ssum;
        #pragma unroll
        for (int j = 0; j < 4; j++) wbuf[wid * 128 + lane + 32 * j] = L[j] * inv;
        __syncwarp();
        // lane owns d = lane
        float acc = 0.f;
        const float* svex = sve + (size_t)(127 - x) * 33 + lane;  // sve[(y-x+127)][lane]
        const float* svd  = sv + lane;
        const float* wrow = wbuf + wid * 128;
        #pragma unroll 4
        for (int y = 0; y < 128; y++) {
            float wv = wrow[y];
            acc = fmaf(wv, svd[y * 33] + svex[y * 33], acc);
        }
        obuf[lane * 129 + x] = acc;
        __syncwarp();
    }
    __syncthreads();
    float* ob = g_attn + (size_t)b * 256 * KK + (size_t)hh * 32 * KK;
    for (int idx = tid; idx < 32 * 128; idx += 256) {
        int d = idx >> 7, xx = idx & 127;
        ob[(size_t)d * KK + xx] = obuf[d * 129 + xx];
    }
}

// ---------------- kernel 7: g_attn [(b0*W+w)][c][h] -> out (B,DEPTH,H,W) ----------------
__global__ void transpose_out(float* __restrict__ out) {
    __shared__ float tile[32][33];
    int plane = blockIdx.z;              // b0*256 + c
    int b0 = plane >> 8, c = plane & 255;
    int h0 = blockIdx.y * 32, w0 = blockIdx.x * 32;
    int tx = threadIdx.x;
    for (int i = threadIdx.y; i < 32; i += 8) {
        int w = w0 + i;
        tile[i][tx] = g_attn[(size_t)(b0 * 128 + w) * 256 * KK + (size_t)c * KK + h0 + tx];
    }
    __syncthreads();
    for (int i = threadIdx.y; i < 32; i += 8) {
        int h = h0 + i;
        out[(size_t)plane * HH * WW + (size_t)h * WW + w0 + tx] = tile[tx][i];
    }
}

// ---------------- launch ----------------
extern "C" void kernel_launch(void* const* d_in, const int* in_sizes, int n_in,
                              void* d_out, int out_size) {
    (void)in_sizes; (void)n_in; (void)out_size;
    const float* x    = (const float*)d_in[0];
    const float* wkqv = (const float*)d_in[1];
    const float* kg   = (const float*)d_in[2];
    const float* kb   = (const float*)d_in[3];
    const float* lg   = (const float*)d_in[4];
    const float* lb   = (const float*)d_in[5];
    const float* rel  = (const float*)d_in[6];
    float* out = (float*)d_out;

    cudaFuncSetAttribute(attn_kernel, cudaFuncAttributeMaxDynamicSharedMemorySize,
                         SMEM_F_FLOATS * (int)sizeof(float));

    dim3 tb(32, 8);
    transpose_x<<<dim3(4, 4, 512), tb>>>(x);
    gemm_kqv<<<dim3(4, 256), 256>>>(wkqv);
    bn_kqv_stats<<<512, 256>>>(kg, kb);
    logits_kernel<<<2048, 256>>>(rel);
    finalize_logits<<<24, 256>>>(lg, lb);
    attn_kernel<<<2048, 256, SMEM_F_FLOATS * sizeof(float)>>>(rel);
    transpose_out<<<dim3(4, 4, 512), tb>>>(out);
}

// round 16
// speedup vs baseline: 1.0075x; 1.0075x over previous
#include <cuda_runtime.h>
#include <math.h>

#define B2 2
#define C 256
#define HH 128
#define WW 128
#define NB (B2*WW)       // 256
#define O2 512           // 2*DEPTH
#define NH 8
#define KK 128
#define REL (2*KK-1)     // 255
#define EPSBN 1e-5f

// ---------------- device scratch ----------------
__device__ float g_xf[(size_t)NB*C*HH];        // [b][c][h]
__device__ float g_kqv[(size_t)NB*O2*HH];      // [b][o][h]
__device__ float g_qk[(size_t)NB*NH*KK*KK];
__device__ float g_qr[(size_t)NB*NH*KK*KK];
__device__ float g_kr[(size_t)NB*NH*KK*KK];
__device__ float g_attn[(size_t)NB*256*KK];    // [b][head*32+d][x]
__device__ float g_ks[O2], g_kt[O2];           // kqv BN scale/shift
__device__ float g_part[NB*NH*6];              // per-(b,head) logits BN partials
__device__ float g_ls[24], g_lt[24];           // logits BN scale/shift

// ---------------- kernel 1: x (B,C,H,W) -> xf [(b0*W+w)][c][h] ----------------
__global__ void transpose_x(const float* __restrict__ x) {
    __shared__ float tile[32][33];
    int plane = blockIdx.z;              // b0*C + c
    int b0 = plane >> 8, c = plane & 255;
    int h0 = blockIdx.y * 32, w0 = blockIdx.x * 32;
    const float* src = x + (size_t)plane * HH * WW;
    int tx = threadIdx.x;
    for (int i = threadIdx.y; i < 32; i += 8)
        tile[i][tx] = src[(size_t)(h0 + i) * WW + w0 + tx];
    __syncthreads();
    for (int i = threadIdx.y; i < 32; i += 8) {
        int w = w0 + i;
        g_xf[(size_t)(b0 * WW + w) * C * HH + (size_t)c * HH + h0 + tx] = tile[tx][i];
    }
}

// ---------------- kernel 2: kqv[b][o][h] = sum_c w[o][c] * xf[b][c][h] ----------------
__global__ void __launch_bounds__(256) gemm_kqv(const float* __restrict__ wkqv) {
    __shared__ float As[16][128];   // [k][o]
    __shared__ float Bs[16][128];   // [k][h]
    int b = blockIdx.y;
    int otile = blockIdx.x;          // 0..3
    int tid = threadIdx.x;
    int tx = tid & 15, ty = tid >> 4;
    const float* xfb = g_xf + (size_t)b * C * HH;
    float acc[8][8];
    #pragma unroll
    for (int i = 0; i < 8; i++)
        #pragma unroll
        for (int j = 0; j < 8; j++) acc[i][j] = 0.f;

    int ai = tid & 127;
    int aj = (tid >> 7) * 8;
    for (int kc = 0; kc < C; kc += 16) {
        const float* wrow = wkqv + (size_t)(otile * 128 + ai) * C + kc + aj;
        float4 a0 = *(const float4*)(wrow);
        float4 a1 = *(const float4*)(wrow + 4);
        As[aj + 0][ai] = a0.x; As[aj + 1][ai] = a0.y;
        As[aj + 2][ai] = a0.z; As[aj + 3][ai] = a0.w;
        As[aj + 4][ai] = a1.x; As[aj + 5][ai] = a1.y;
        As[aj + 6][ai] = a1.z; As[aj + 7][ai] = a1.w;
        #pragma unroll
        for (int t = 0; t < 2; t++) {
            int l = tid + t * 256;       // 0..511
            int j = l >> 5;              // 0..15
            int h4 = (l & 31) * 4;
            *(float4*)&Bs[j][h4] = *(const float4*)(xfb + (size_t)(kc + j) * HH + h4);
        }
        __syncthreads();
        #pragma unroll
        for (int k = 0; k < 16; k++) {
            float af[8], bf[8];
            *(float4*)(af)     = *(float4*)&As[k][ty * 8];
            *(float4*)(af + 4) = *(float4*)&As[k][ty * 8 + 4];
            *(float4*)(bf)     = *(float4*)&Bs[k][tx * 8];
            *(float4*)(bf + 4) = *(float4*)&Bs[k][tx * 8 + 4];
            #pragma unroll
            for (int i = 0; i < 8; i++)
                #pragma unroll
                for (int j = 0; j < 8; j++)
                    acc[i][j] = fmaf(af[i], bf[j], acc[i][j]);
        }
        __syncthreads();
    }
    float* outb = g_kqv + (size_t)b * O2 * HH + (size_t)(otile * 128) * HH;
    #pragma unroll
    for (int i = 0; i < 8; i++) {
        float* row = outb + (size_t)(ty * 8 + i) * HH + tx * 8;
        *(float4*)(row)     = *(float4*)&acc[i][0];
        *(float4*)(row + 4) = *(float4*)&acc[i][4];
    }
}

// ---------------- kernel 3: kqv BN stats per channel o ----------------
__global__ void bn_kqv_stats(const float* __restrict__ gamma, const float* __restrict__ beta) {
    int o = blockIdx.x;
    float s = 0.f, sq = 0.f;
    for (int idx = threadIdx.x; idx < NB * HH; idx += 256) {
        int b = idx >> 7, h = idx & 127;
        float v = g_kqv[(size_t)b * O2 * HH + (size_t)o * HH + h];
        s += v; sq += v * v;
    }
    __shared__ float rs[8], rq[8];
    int wid = threadIdx.x >> 5, lane = threadIdx.x & 31;
    #pragma unroll
    for (int off = 16; off; off >>= 1) {
        s  += __shfl_down_sync(0xffffffffu, s, off);
        sq += __shfl_down_sync(0xffffffffu, sq, off);
    }
    if (!lane) { rs[wid] = s; rq[wid] = sq; }
    __syncthreads();
    if (threadIdx.x == 0) {
        float ts = 0.f, tq = 0.f;
        #pragma unroll
        for (int w = 0; w < 8; w++) { ts += rs[w]; tq += rq[w]; }
        float n = (float)(NB * HH);
        float mean = ts / n;
        float var = tq / n - mean * mean;
        float sc = gamma[o] * rsqrtf(var + EPSBN);
        g_ks[o] = sc;
        g_kt[o] = beta[o] - mean * sc;
    }
}

// ---------------- kernel 4: logits qk/qr/kr per (b, head) + BN partials ----------------
__global__ void __launch_bounds__(256) logits_kernel(const float* __restrict__ rel) {
    __shared__ float sq[16][128], sk[16][128];
    __shared__ float sqe[16][REL], ske[16][REL];
    int bh = blockIdx.x;
    int b = bh >> 3, hh = bh & 7;
    int tid = threadIdx.x;
    const float* kqvb = g_kqv + (size_t)b * O2 * HH;

    for (int idx = tid; idx < 16 * 128; idx += 256) {
        int d = idx >> 7, h = idx & 127;
        int ok = hh * 64 + d;
        int oq = ok + 16;
        sk[d][h] = kqvb[(size_t)ok * HH + h] * g_ks[ok] + g_kt[ok];
        sq[d][h] = kqvb[(size_t)oq * HH + h] * g_ks[oq] + g_kt[oq];
    }
    for (int idx = tid; idx < 16 * REL; idx += 256) {
        int d = idx / REL, i = idx % REL;
        sqe[d][i] = rel[(size_t)d * REL + i];
        ske[d][i] = rel[(size_t)(16 + d) * REL + i];
    }
    __syncthreads();

    float aqk = 0, aqk2 = 0, aqr = 0, aqr2 = 0, akr = 0, akr2 = 0;
    int wid = tid >> 5, lane = tid & 31;
    size_t base = (size_t)bh * KK * KK;
    for (int r = 0; r < 16; r++) {
        int x = wid * 16 + r;
        float qreg[16];
        #pragma unroll
        for (int d = 0; d < 16; d++) qreg[d] = sq[d][x];
        #pragma unroll
        for (int j = 0; j < 4; j++) {
            int y = lane + 32 * j;
            int iq = y - x + 127;
            int ik = x - y + 127;
            float vqk = 0.f, vqr = 0.f, vkr = 0.f;
            #pragma unroll
            for (int d = 0; d < 16; d++) {
                float kd = sk[d][y];
                vqk = fmaf(qreg[d], kd, vqk);
                vqr = fmaf(qreg[d], sqe[d][iq], vqr);
                vkr = fmaf(kd, ske[d][ik], vkr);
            }
            size_t oidx = base + (size_t)x * KK + y;
            g_qk[oidx] = vqk;
            g_qr[oidx] = vqr;
            g_kr[oidx] = vkr;
            aqk += vqk; aqk2 = fmaf(vqk, vqk, aqk2);
            aqr += vqr; aqr2 = fmaf(vqr, vqr, aqr2);
            akr += vkr; akr2 = fmaf(vkr, vkr, akr2);
        }
    }
    // block reduction of 6 partials (deterministic; no atomics)
    float vals[6] = {aqk, aqk2, aqr, aqr2, akr, akr2};
    #pragma unroll
    for (int v = 0; v < 6; v++)
        #pragma unroll
        for (int off = 16; off; off >>= 1)
            vals[v] += __shfl_down_sync(0xffffffffu, vals[v], off);
    __syncthreads();                 // everyone done reading sq
    float* red = &sq[0][0];          // reuse smem (8 warps * 6)
    if (!lane) {
        #pragma unroll
        for (int v = 0; v < 6; v++) red[wid * 6 + v] = vals[v];
    }
    __syncthreads();
    if (tid < 6) {
        float t = 0.f;
        #pragma unroll
        for (int w = 0; w < 8; w++) t += red[w * 6 + tid];
        g_part[(size_t)bh * 6 + tid] = t;   // order: qk_s,qk_q, qr_s,qr_q, kr_s,kr_q
    }
}

// ---------------- kernel 5: finalize logits BN (deterministic) ----------------
__global__ void finalize_logits(const float* __restrict__ lg, const float* __restrict__ lb) {
    int c = blockIdx.x;              // 0..23
    int comp = c >> 3, hh = c & 7;
    int t = threadIdx.x;             // 0..255 -> b
    float s  = g_part[(size_t)(t * 8 + hh) * 6 + comp * 2];
    float sq = g_part[(size_t)(t * 8 + hh) * 6 + comp * 2 + 1];
    __shared__ float rs[8], rq[8];
    int wid = t >> 5, lane = t & 31;
    #pragma unroll
    for (int off = 16; off; off >>= 1) {
        s  += __shfl_down_sync(0xffffffffu, s, off);
        sq += __shfl_down_sync(0xffffffffu, sq, off);
    }
    if (!lane) { rs[wid] = s; rq[wid] = sq; }
    __syncthreads();
    if (t == 0) {
        float ts = 0.f, tq = 0.f;
        #pragma unroll
        for (int w = 0; w < 8; w++) { ts += rs[w]; tq += rq[w]; }
        float n = (float)NB * KK * KK;   // 4194304
        float mean = ts / n;
        float var = tq / n - mean * mean;
        float sc = lg[c] * rsqrtf(var + EPSBN);
        g_ls[c] = sc;
        g_lt[c] = lb[c] - mean * sc;
    }
}

// ---------------- kernel 6: softmax + attn + attn_enc per (b, head) ----------------
#define SMEM_F_FLOATS (128*33 + 255*33 + 8*128 + 32*129)
__global__ void __launch_bounds__(256) attn_kernel(const float* __restrict__ rel) {
    extern __shared__ float smemF[];
    float* sv   = smemF;                  // [y][d] stride 33
    float* sve  = sv + 128 * 33;          // [idx][d] stride 33
    float* wbuf = sve + 255 * 33;         // [warp][y] stride 128
    float* obuf = wbuf + 8 * 128;         // [d][x] stride 129

    int bh = blockIdx.x;
    int b = bh >> 3, hh = bh & 7;
    int tid = threadIdx.x;
    const float* kqvb = g_kqv + (size_t)b * O2 * HH;

    for (int idx = tid; idx < 32 * 128; idx += 256) {
        int d = idx >> 7, y = idx & 127;
        int o = hh * 64 + 32 + d;
        sv[y * 33 + d] = kqvb[(size_t)o * HH + y] * g_ks[o] + g_kt[o];
    }
    for (int idx = tid; idx < 32 * REL; idx += 256) {
        int d = idx / REL, i = idx % REL;
        sve[i * 33 + d] = rel[(size_t)(32 + d) * REL + i];
    }
    float s0 = g_ls[hh], s1 = g_ls[8 + hh], s2 = g_ls[16 + hh];
    float tt = g_lt[hh] + g_lt[8 + hh] + g_lt[16 + hh];
    __syncthreads();

    int wid = tid >> 5, lane = tid & 31;
    size_t base = (size_t)bh * KK * KK;
    for (int r = 0; r < 16; r++) {
        int x = wid * 16 + r;
        float L[4];
        #pragma unroll
        for (int j = 0; j < 4; j++) {
            size_t idx = base + (size_t)x * KK + lane + 32 * j;
            L[j] = g_qk[idx] * s0 + g_qr[idx] * s1 + g_kr[idx] * s2 + tt;
        }
        float m = fmaxf(fmaxf(L[0], L[1]), fmaxf(L[2], L[3]));
        #pragma unroll
        for (int off = 16; off; off >>= 1)
            m = fmaxf(m, __shfl_xor_sync(0xffffffffu, m, off));
        float ssum = 0.f;
        #pragma unroll
        for (int j = 0; j < 4; j++) { L[j] = expf(L[j] - m); ssum += L[j]; }
        #pragma unroll
        for (int off = 16; off; off >>= 1)
            ssum += __shfl_xor_sync(0xffffffffu, ssum, off);
        float inv = 1.0f / ssum;
        #pragma unroll
        for (int j = 0; j < 4; j++) wbuf[wid * 128 + lane + 32 * j] = L[j] * inv;
        __syncwarp();
        // lane owns d = lane
        float acc = 0.f;
        const float* svex = sve + (size_t)(127 - x) * 33 + lane;  // sve[(y-x+127)][lane]
        const float* svd  = sv + lane;
        const float* wrow = wbuf + wid * 128;
        #pragma unroll 4
        for (int y = 0; y < 128; y++) {
            float wv = wrow[y];
            acc = fmaf(wv, svd[y * 33] + svex[y * 33], acc);
        }
        obuf[lane * 129 + x] = acc;
        __syncwarp();
    }
    __syncthreads();
    float* ob = g_attn + (size_t)b * 256 * KK + (size_t)hh * 32 * KK;
    for (int idx = tid; idx < 32 * 128; idx += 256) {
        int d = idx >> 7, xx = idx & 127;
        ob[(size_t)d * KK + xx] = obuf[d * 129 + xx];
    }
}

// ---------------- kernel 7: g_attn [(b0*W+w)][c][h] -> out (B,DEPTH,H,W) ----------------
__global__ void transpose_out(float* __restrict__ out) {
    __shared__ float tile[32][33];
    int plane = blockIdx.z;              // b0*256 + c
    int b0 = plane >> 8, c = plane & 255;
    int h0 = blockIdx.y * 32, w0 = blockIdx.x * 32;
    int tx = threadIdx.x;
    for (int i = threadIdx.y; i < 32; i += 8) {
        int w = w0 + i;
        tile[i][tx] = g_attn[(size_t)(b0 * 128 + w) * 256 * KK + (size_t)c * KK + h0 + tx];
    }
    __syncthreads();
    for (int i = threadIdx.y; i < 32; i += 8) {
        int h = h0 + i;
        out[(size_t)plane * HH * WW + (size_t)h * WW + w0 + tx] = tile[tx][i];
    }
}

// ---------------- launch ----------------
extern "C" void kernel_launch(void* const* d_in, const int* in_sizes, int n_in,
                              void* d_out, int out_size) {
    (void)in_sizes; (void)n_in; (void)out_size;
    const float* x    = (const float*)d_in[0];
    const float* wkqv = (const float*)d_in[1];
    const float* kg   = (const float*)d_in[2];
    const float* kb   = (const float*)d_in[3];
    const float* lg   = (const float*)d_in[4];
    const float* lb   = (const float*)d_in[5];
    const float* rel  = (const float*)d_in[6];
    float* out = (float*)d_out;

    cudaFuncSetAttribute(attn_kernel, cudaFuncAttributeMaxDynamicSharedMemorySize,
                         SMEM_F_FLOATS * (int)sizeof(float));

    dim3 tb(32, 8);
    transpose_x<<<dim3(4, 4, 512), tb>>>(x);
    gemm_kqv<<<dim3(4, 256), 256>>>(wkqv);
    bn_kqv_stats<<<512, 256>>>(kg, kb);
    logits_kernel<<<2048, 256>>>(rel);
    finalize_logits<<<24, 256>>>(lg, lb);
    attn_kernel<<<2048, 256, SMEM_F_FLOATS * sizeof(float)>>>(rel);
    transpose_out<<<dim3(4, 4, 512), tb>>>(out);
}